// round 16
// baseline (speedup 1.0000x reference)
#include <cuda_runtime.h>
#include <cstdint>

// Problem constants
#define B_  32
#define H_  4
#define L_  2048
#define D_  64
#define N_  32
#define P_  64
#define WN  63          // win_num
#define II  64          // N * win

#define WX_ELEMS 33030144   // B*H*II*WN*D
#define M_V      129024     // B*II*WN
#define NBHW     8064       // B*H*WN
#define OUT_ELEMS 16777216  // B*L*H*D

#define XS 68                              // uint2 row stride (2*68==8 mod 32: all frag patterns conflict-free)
#define AS2 136                            // Abuf float row stride (== XS uint2)
#define SMEM_QK (2 * 64 * XS * 8 + 128 * 4)   // 70144 B

// Scratch (static device globals — allocation-free per harness rules)
__device__ float g_wx[WX_ELEMS];   // [b][h][i][w][d]
__device__ float g_v [WX_ELEMS];   // [b][i][w][h*64+d]
__device__ float g_adj[WX_ELEMS];  // [b][h][w][i][j]
__device__ __align__(16) uint2 g_mp[4096];    // M = W1 W2^T, tf32 {hi,lo}
__device__ float g_uvs[130];                  // u[64], v[64], s=b1.b2

// ---------------------------------------------------------------------------
// tf32 helpers
// ---------------------------------------------------------------------------
__device__ __forceinline__ uint32_t f2tf32(float x) {
    uint32_t r;
    asm("cvt.rna.tf32.f32 %0, %1;" : "=r"(r) : "f"(x));
    return r;
}
__device__ __forceinline__ void split_tf32(float x, uint32_t& hi, uint32_t& lo) {
    asm("cvt.rna.tf32.f32 %0, %1;" : "=r"(hi) : "f"(x));
    float l = x - __uint_as_float(hi);
    asm("cvt.rna.tf32.f32 %0, %1;" : "=r"(lo) : "f"(l));
}
__device__ __forceinline__ void mma8(float* d, const uint32_t* a, const uint32_t* b) {
    asm volatile(
        "mma.sync.aligned.m16n8k8.row.col.f32.tf32.tf32.f32 "
        "{%0,%1,%2,%3}, {%4,%5,%6,%7}, {%8,%9}, {%0,%1,%2,%3};"
        : "+f"(d[0]), "+f"(d[1]), "+f"(d[2]), "+f"(d[3])
        : "r"(a[0]), "r"(a[1]), "r"(a[2]), "r"(a[3]), "r"(b[0]), "r"(b[1]));
}
// 3xTF32: d += a*b with near-fp32 accuracy (lo*hi + hi*lo + hi*hi)
__device__ __forceinline__ void mma3(float* d, const uint32_t* ah, const uint32_t* al,
                                     const uint32_t* bh, const uint32_t* bl) {
    mma8(d, al, bh);
    mma8(d, ah, bl);
    mma8(d, ah, bh);
}

// ---------------------------------------------------------------------------
// 0. k_prep (one block): M = W1 W2^T (fp32 -> tf32 {hi,lo}), u = W1 b2,
//    v = W2 b1, s = b1.b2.   A = X M X^T + (Xu)⊗1 + 1⊗(Xv) + s.
// ---------------------------------------------------------------------------
__global__ __launch_bounds__(256) void k_prep(const float* __restrict__ W1,
                                              const float* __restrict__ b1,
                                              const float* __restrict__ W2,
                                              const float* __restrict__ b2) {
    __shared__ float W1s[64][65];
    __shared__ float W2s[64][65];
    int t = threadIdx.x;
#pragma unroll
    for (int it = 0; it < 16; ++it) {
        int i2 = t + it * 256;
        W1s[i2 >> 6][i2 & 63] = W1[i2];
        W2s[i2 >> 6][i2 & 63] = W2[i2];
    }
    __syncthreads();
    int d1 = t >> 2, part = t & 3;
#pragma unroll
    for (int m = 0; m < 16; ++m) {
        int d2 = part * 16 + m;
        float s = 0.f;
#pragma unroll 8
        for (int dd = 0; dd < 64; ++dd) s += W1s[d1][dd] * W2s[d2][dd];
        uint32_t hi, lo;
        split_tf32(s, hi, lo);
        g_mp[d1 * 64 + d2] = make_uint2(hi, lo);
    }
    if (t < 64) {
        float su = 0.f, sv = 0.f;
#pragma unroll 8
        for (int dd = 0; dd < 64; ++dd) {
            su += W1s[t][dd] * b2[dd];
            sv += W2s[t][dd] * b1[dd];
        }
        g_uvs[t] = su;
        g_uvs[64 + t] = sv;
    }
    if (t == 0) {
        float s = 0.f;
        for (int dd = 0; dd < 64; ++dd) s += b1[dd] * b2[dd];
        g_uvs[128] = s;
    }
}

// ---------------------------------------------------------------------------
// 1. Gather wx, coalesced: one block per (bh, n); stage 64x64 x-tile in smem.
// ---------------------------------------------------------------------------
__global__ __launch_bounds__(256) void k_build_wx(const float* __restrict__ x) {
    __shared__ float xs[65][65];     // 65 rows: row w+1 valid for w=63 never used (w<=62, e<=1 -> row<=63)
    int bid = blockIdx.x;            // bh*32 + n, 4096 blocks
    int bh  = bid >> 5;
    int n   = bid & 31;
    int tid = threadIdx.x;
#pragma unroll
    for (int it = 0; it < 16; ++it) {
        int i2 = tid + it * 256;
        int rr = i2 >> 6, cc = i2 & 63;
        xs[rr][cc] = x[(bh * L_ + n * P_ + rr) * D_ + cc];
    }
    __syncthreads();
    float2* dst = (float2*)(g_wx + bh * 258048 + n * 8064);
    for (int j2 = tid; j2 < 4032; j2 += 256) {
        int j  = j2 * 2;
        int d  = j / 126;
        int r2 = j - d * 126;
        int w  = r2 >> 1;            // r2 even
        dst[j2] = make_float2(xs[w][d], xs[w + 1][d]);
    }
}

// ---------------------------------------------------------------------------
// 2. Fused per (b,h,w): T = X M (3xTF32), A = T X^T (3xTF32) + Xu_i + Xv_j + s,
//    top-32 |.| keep via ballot-quickselect threshold, tanh, L1 row-normalize.
//    X and M/T stored as interleaved uint2{hi,lo} at stride 68: one LDS.64
//    per fragment element, all patterns bank-conflict-free.
// ---------------------------------------------------------------------------
__global__ __launch_bounds__(256) void k_qk_adj() {
    extern __shared__ uint2 dyn_q[];
    uint2* Xp = dyn_q;                 // 64*XS  (X {hi,lo}; later Abuf fp32)
    uint2* Mp = Xp + 64 * XS;          // 64*XS  (M {hi,lo} -> T {hi,lo})
    float* xu = (float*)(Mp + 64 * XS);   // 64 (includes +s)
    float* xv = xu + 64;                  // 64

    int tid = threadIdx.x;
    int bid = blockIdx.x;
    int w   = bid % WN;
    int bh  = bid / WN;
#pragma unroll
    for (int it = 0; it < 4; ++it) {
        int i4 = tid + it * 256;
        int rr = i4 >> 4, c4 = (i4 & 15) * 4;
        float4 v = *(const float4*)&g_wx[((bh * II + rr) * WN + w) * D_ + c4];
        uint32_t h0, l0, h1, l1, h2, l2, h3, l3;
        split_tf32(v.x, h0, l0);
        split_tf32(v.y, h1, l1);
        split_tf32(v.z, h2, l2);
        split_tf32(v.w, h3, l3);
        *(uint4*)&Xp[rr * XS + c4]     = make_uint4(h0, l0, h1, l1);
        *(uint4*)&Xp[rr * XS + c4 + 2] = make_uint4(h2, l2, h3, l3);
        *(uint4*)&Mp[rr * XS + c4]     = *(const uint4*)&g_mp[rr * 64 + c4];
        *(uint4*)&Mp[rr * XS + c4 + 2] = *(const uint4*)&g_mp[rr * 64 + c4 + 2];
    }
    __syncthreads();

    // Xu[i] = X[i].u + s ; Xv[i] = X[i].v   (4 threads per row)
    {
        int r = tid >> 2, q = tid & 3;
        float su = 0.f, sv = 0.f;
#pragma unroll
        for (int k = 0; k < 16; ++k) {
            int d = q * 16 + k;
            uint2 xp = Xp[r * XS + d];
            float xval = __uint_as_float(xp.x) + __uint_as_float(xp.y);
            su += xval * g_uvs[d];
            sv += xval * g_uvs[64 + d];
        }
        su += __shfl_xor_sync(0xffffffffu, su, 1);
        su += __shfl_xor_sync(0xffffffffu, su, 2);
        sv += __shfl_xor_sync(0xffffffffu, sv, 1);
        sv += __shfl_xor_sync(0xffffffffu, sv, 2);
        if (q == 0) { xu[r] = su + g_uvs[128]; xv[r] = sv; }
    }

    int warp = tid >> 5, lane = tid & 31;
    int g = lane >> 2, tq = lane & 3;
    int ms = (warp & 3) * 16;
    int nh = (warp >> 2) * 32;
    int r0 = (ms + g) * XS, r1 = (ms + g + 8) * XS;

    // ---- Phase A: T = X @ M. Warp tile 16 x 32.
    {
        float acc[4][4];
#pragma unroll
        for (int nt = 0; nt < 4; ++nt)
#pragma unroll
            for (int c = 0; c < 4; ++c) acc[nt][c] = 0.f;
#pragma unroll
        for (int ks = 0; ks < 8; ++ks) {
            int k0 = ks * 8;
            uint2 a0 = Xp[r0 + k0 + tq];
            uint2 a1 = Xp[r1 + k0 + tq];
            uint2 a2 = Xp[r0 + k0 + tq + 4];
            uint2 a3 = Xp[r1 + k0 + tq + 4];
            uint32_t ah[4] = {a0.x, a1.x, a2.x, a3.x};
            uint32_t al[4] = {a0.y, a1.y, a2.y, a3.y};
            int b0 = (k0 + tq) * XS, b4 = (k0 + tq + 4) * XS;
#pragma unroll
            for (int nt = 0; nt < 4; ++nt) {
                int cb = nh + nt * 8 + g;
                uint2 m0 = Mp[b0 + cb];
                uint2 m1 = Mp[b4 + cb];
                uint32_t bhv[2] = {m0.x, m1.x};
                uint32_t blv[2] = {m0.y, m1.y};
                mma3(acc[nt], ah, al, bhv, blv);
            }
        }
        __syncthreads();   // all M reads done before T overwrites the buffer
#pragma unroll
        for (int nt = 0; nt < 4; ++nt) {
            int n0 = nh + nt * 8 + 2 * tq;
            uint32_t h0, l0, h1, l1;
            split_tf32(acc[nt][0], h0, l0);
            split_tf32(acc[nt][1], h1, l1);
            *(uint4*)&Mp[(ms + g) * XS + n0] = make_uint4(h0, l0, h1, l1);
            split_tf32(acc[nt][2], h0, l0);
            split_tf32(acc[nt][3], h1, l1);
            *(uint4*)&Mp[(ms + g + 8) * XS + n0] = make_uint4(h0, l0, h1, l1);
        }
        __syncthreads();
    }

    // ---- Phase B: A = T @ X^T. Warp tile 16 x 32.
    float* Abuf = (float*)Xp;      // written only after sync below
    {
        float acc[4][4];
#pragma unroll
        for (int nt = 0; nt < 4; ++nt)
#pragma unroll
            for (int c = 0; c < 4; ++c) acc[nt][c] = 0.f;
#pragma unroll
        for (int ks = 0; ks < 8; ++ks) {
            int k0 = ks * 8;
            uint2 a0 = Mp[r0 + k0 + tq];
            uint2 a1 = Mp[r1 + k0 + tq];
            uint2 a2 = Mp[r0 + k0 + tq + 4];
            uint2 a3 = Mp[r1 + k0 + tq + 4];
            uint32_t ah[4] = {a0.x, a1.x, a2.x, a3.x};
            uint32_t al[4] = {a0.y, a1.y, a2.y, a3.y};
#pragma unroll
            for (int nt = 0; nt < 4; ++nt) {
                int j0 = (nh + nt * 8 + g) * XS;
                uint2 x0 = Xp[j0 + k0 + tq];
                uint2 x1 = Xp[j0 + k0 + tq + 4];
                uint32_t bhv[2] = {x0.x, x1.x};
                uint32_t blv[2] = {x0.y, x1.y};
                mma3(acc[nt], ah, al, bhv, blv);
            }
        }
        __syncthreads();   // all X reads done before A overwrites Xp
#pragma unroll
        for (int nt = 0; nt < 4; ++nt) {
            int n0 = nh + nt * 8 + 2 * tq;
            float v0 = xv[n0], v1 = xv[n0 + 1];
            *(float2*)&Abuf[(ms + g) * AS2 + n0] =
                make_float2(acc[nt][0] + xu[ms + g] + v0,
                            acc[nt][1] + xu[ms + g] + v1);
            *(float2*)&Abuf[(ms + g + 8) * AS2 + n0] =
                make_float2(acc[nt][2] + xu[ms + g + 8] + v0,
                            acc[nt][3] + xu[ms + g + 8] + v1);
        }
        __syncthreads();
    }

    // ---- ranking: ballot-quickselect threshold t = 32nd-smallest |a|;
    //      keep iff |a| > t  (== count rule); tanh; L1 normalize ----
    const unsigned FULL = 0xffffffffu;
    int adjbase = bid * 4096;
    for (int r8 = 0; r8 < 8; ++r8) {
        int row = warp * 8 + r8;
        float a1 = Abuf[row * AS2 + lane];
        float a2 = Abuf[row * AS2 + lane + 32];
        float k0 = fabsf(a1), k1 = fabsf(a2);
        float lo = -1.f, hi = __int_as_float(0x7f800000);
        float t = hi;
        for (int it = 0; it < 64; ++it) {
            unsigned m0 = __ballot_sync(FULL, k0 > lo && k0 < hi);
            float piv;
            if (m0) {
                piv = __shfl_sync(FULL, k0, __ffs(m0) - 1);
            } else {
                unsigned m1 = __ballot_sync(FULL, k1 > lo && k1 < hi);
                if (!m1) break;                 // safety; unreachable
                piv = __shfl_sync(FULL, k1, __ffs(m1) - 1);
            }
            int c = __popc(__ballot_sync(FULL, k0 < piv)) +
                    __popc(__ballot_sync(FULL, k1 < piv));
            if (c > 31) {
                hi = piv;
            } else {
                int cle = __popc(__ballot_sync(FULL, k0 <= piv)) +
                          __popc(__ballot_sync(FULL, k1 <= piv));
                if (cle >= 32) { t = piv; break; }
                lo = piv;
            }
        }
        float t1 = (k0 > t) ? tanhf(a1) : 0.f;
        float t2 = (k1 > t) ? tanhf(a2) : 0.f;
        float s = fabsf(t1) + fabsf(t2);
#pragma unroll
        for (int off = 16; off; off >>= 1) s += __shfl_xor_sync(FULL, s, off);
        float inv = 1.f / fmaxf(s, 1e-12f);
        g_adj[adjbase + row * 64 + lane]      = t1 * inv;
        g_adj[adjbase + row * 64 + lane + 32] = t2 * inv;
    }
}

// ---------------------------------------------------------------------------
// 3. v = v_in @ Wv + bv  (1xTF32). 64 rows x 256 cols per block.
// ---------------------------------------------------------------------------
__global__ __launch_bounds__(256) void k_v2(const float* __restrict__ Wv,
                                            const float* __restrict__ bv) {
    __shared__ uint32_t As[64 * 36];
    __shared__ __align__(16) uint32_t Bs[32 * 264];
    int tid  = threadIdx.x;
    int m0   = blockIdx.x * 64;
    int b    = blockIdx.x / 63;
    int rem0 = (blockIdx.x - b * 63) * 64;
    int warp = tid >> 5, lane = tid & 31;
    int g = lane >> 2, tq = lane & 3;
    int ms = (warp & 3) * 16;
    int nh = (warp >> 2) * 128;
    float acc[16][4];
#pragma unroll
    for (int nt = 0; nt < 16; ++nt)
#pragma unroll
        for (int c = 0; c < 4; ++c) acc[nt][c] = 0.f;

    for (int ch = 0; ch < 8; ++ch) {       // global k = ch*32 + kk; h = ch>>1
#pragma unroll
        for (int it = 0; it < 2; ++it) {   // A: 64x32, float4 + cvt tf32
            int i4 = tid + it * 256;
            int rr = i4 >> 3, c4 = (i4 & 7) * 4;
            int rem = rem0 + rr;
            int i  = rem / WN;
            int ww = rem - i * WN;
            float4 v = *(const float4*)&g_wx[
                (((b * H_ + (ch >> 1)) * II + i) * WN + ww) * D_ +
                (ch & 1) * 32 + c4];
            As[rr * 36 + c4 + 0] = f2tf32(v.x);
            As[rr * 36 + c4 + 1] = f2tf32(v.y);
            As[rr * 36 + c4 + 2] = f2tf32(v.z);
            As[rr * 36 + c4 + 3] = f2tf32(v.w);
        }
#pragma unroll
        for (int it = 0; it < 8; ++it) {   // B: 32x256, cvt tf32 at store
            int i4 = tid + it * 256;
            int r  = i4 >> 6;
            int c  = (i4 & 63) * 4;
            float4 v4 = *(const float4*)&Wv[(ch * 32 + r) * 256 + c];
            uint4 t;
            t.x = f2tf32(v4.x); t.y = f2tf32(v4.y);
            t.z = f2tf32(v4.z); t.w = f2tf32(v4.w);
            *(uint4*)&Bs[r * 264 + c] = t;
        }
        __syncthreads();
#pragma unroll
        for (int ks = 0; ks < 4; ++ks) {
            int k0 = ks * 8;
            uint32_t a[4];
            a[0] = As[(ms + g) * 36 + k0 + tq];
            a[1] = As[(ms + g + 8) * 36 + k0 + tq];
            a[2] = As[(ms + g) * 36 + k0 + tq + 4];
            a[3] = As[(ms + g + 8) * 36 + k0 + tq + 4];
#pragma unroll
            for (int nt = 0; nt < 16; ++nt) {
                int n0 = nh + nt * 8 + g;
                uint32_t bb[2];
                bb[0] = Bs[(k0 + tq) * 264 + n0];
                bb[1] = Bs[(k0 + tq + 4) * 264 + n0];
                mma8(acc[nt], a, bb);
            }
        }
        __syncthreads();
    }
#pragma unroll
    for (int nt = 0; nt < 16; ++nt) {
        int n0 = nh + nt * 8 + 2 * tq;
        float bb0 = bv[n0], bb1 = bv[n0 + 1];
        g_v[(m0 + ms + g) * 256 + n0]         = acc[nt][0] + bb0;
        g_v[(m0 + ms + g) * 256 + n0 + 1]     = acc[nt][1] + bb1;
        g_v[(m0 + ms + g + 8) * 256 + n0]     = acc[nt][2] + bb0;
        g_v[(m0 + ms + g + 8) * 256 + n0 + 1] = acc[nt][3] + bb1;
    }
}

// ---------------------------------------------------------------------------
// 4. loss = mean_{b,h,i,j} var_w(adj)   (ddof=0, two-pass)
// ---------------------------------------------------------------------------
__global__ void k_loss_zero(float* __restrict__ out) { out[OUT_ELEMS] = 0.f; }

__global__ __launch_bounds__(256) void k_loss(float* __restrict__ out) {
    int idx = blockIdx.x * 256 + threadIdx.x;  // over B*H*64*64 = 524288
    int bh  = idx >> 12;
    int ij  = idx & 4095;
    const float* p = g_adj + bh * (WN * 4096) + ij;
    float s1 = 0.f;
#pragma unroll 7
    for (int w = 0; w < WN; ++w) s1 += p[w * 4096];
    float m = s1 * (1.f / 63.f);
    float s2 = 0.f;
#pragma unroll 7
    for (int w = 0; w < WN; ++w) { float dv = p[w * 4096] - m; s2 += dv * dv; }
    float var = s2 * (1.f / 63.f);
    __shared__ float red[256];
    red[threadIdx.x] = var;
    __syncthreads();
    for (int off = 128; off; off >>= 1) {
        if (threadIdx.x < off) red[threadIdx.x] += red[threadIdx.x + off];
        __syncthreads();
    }
    if (threadIdx.x == 0) atomicAdd(out + OUT_ELEMS, red[0] * (1.f / 524288.f));
}

// ---------------------------------------------------------------------------
// 5. Fused O-GEMM + epilogue. One block per (bh, 8-p group): computes the
//    needed O[w] tiles (incl. one boundary recompute), keeps previous tile's
//    odd rows in smem, emits out directly.
// ---------------------------------------------------------------------------
__global__ __launch_bounds__(256) void k_out2(float* __restrict__ out_) {
    __shared__ uint32_t As[64 * 68];
    __shared__ uint32_t Vs[64 * 72];
    __shared__ float Oodd[32 * 68];

    int tid = threadIdx.x;
    int bh  = blockIdx.x >> 3;
    int gix = blockIdx.x & 7;
    int b = bh >> 2, h = bh & 3;
    int w0  = gix * 8;
    int wlo = (gix == 0) ? 0 : w0 - 1;
    int whi = (w0 + 7 > 62) ? 62 : w0 + 7;
    int warp = tid >> 5, lane = tid & 31;
    int g = lane >> 2, tq = lane & 3;
    int ms = (warp & 3) * 16;
    int nh = (warp >> 2) * 32;

    for (int w = wlo; w <= whi; ++w) {
        int bidw = bh * WN + w;
#pragma unroll
        for (int it = 0; it < 4; ++it) {
            int i4 = tid + it * 256;
            int rr = i4 >> 4, c4 = (i4 & 15) * 4;
            float4 a4 = *(const float4*)&g_adj[bidw * 4096 + rr * 64 + c4];
            As[rr * 68 + c4 + 0] = f2tf32(a4.x);
            As[rr * 68 + c4 + 1] = f2tf32(a4.y);
            As[rr * 68 + c4 + 2] = f2tf32(a4.z);
            As[rr * 68 + c4 + 3] = f2tf32(a4.w);
            float4 v4 = *(const float4*)&g_v[((b * II + rr) * WN + w) * 256 + h * 64 + c4];
            Vs[rr * 72 + c4 + 0] = f2tf32(v4.x);
            Vs[rr * 72 + c4 + 1] = f2tf32(v4.y);
            Vs[rr * 72 + c4 + 2] = f2tf32(v4.z);
            Vs[rr * 72 + c4 + 3] = f2tf32(v4.w);
        }
        __syncthreads();

        float acc[4][4];
#pragma unroll
        for (int nt = 0; nt < 4; ++nt)
#pragma unroll
            for (int c = 0; c < 4; ++c) acc[nt][c] = 0.f;
#pragma unroll
        for (int ks = 0; ks < 8; ++ks) {
            int k0 = ks * 8;
            uint32_t a[4];
            a[0] = As[(ms + g) * 68 + k0 + tq];
            a[1] = As[(ms + g + 8) * 68 + k0 + tq];
            a[2] = As[(ms + g) * 68 + k0 + tq + 4];
            a[3] = As[(ms + g + 8) * 68 + k0 + tq + 4];
#pragma unroll
            for (int nt = 0; nt < 4; ++nt) {
                int n0 = nh + nt * 8 + g;
                uint32_t bb[2];
                bb[0] = Vs[(k0 + tq) * 72 + n0];
                bb[1] = Vs[(k0 + tq + 4) * 72 + n0];
                mma8(acc[nt], a, bb);
            }
        }

        // emit out[p=w] from even rows (+ previous tile's odd rows)
        if (w >= w0) {
            int p = w;
#pragma unroll
            for (int half = 0; half < 2; ++half) {
                int r = ms + g + half * 8;
                if ((r & 1) == 0) {
                    int n = r >> 1;
                    float* op = out_ + ((size_t)(b * 2048 + n * 64 + p)) * 256 + h * 64;
#pragma unroll
                    for (int nt = 0; nt < 4; ++nt) {
                        int c0 = nh + nt * 8 + 2 * tq;
                        float v0 = acc[nt][half * 2 + 0];
                        float v1 = acc[nt][half * 2 + 1];
                        if (p == 0) {
                            op[c0] = v0;  op[c0 + 1] = v1;
                        } else {
                            op[c0]     = 0.5f * (v0 + Oodd[n * 68 + c0]);
                            op[c0 + 1] = 0.5f * (v1 + Oodd[n * 68 + c0 + 1]);
                        }
                    }
                }
            }
        }
        __syncthreads();   // Oodd reads done before overwrite

        // store this tile's odd rows for the next p
#pragma unroll
        for (int half = 0; half < 2; ++half) {
            int r = ms + g + half * 8;
            if (r & 1) {
                int n = r >> 1;
#pragma unroll
                for (int nt = 0; nt < 4; ++nt) {
                    int c0 = nh + nt * 8 + 2 * tq;
                    Oodd[n * 68 + c0]     = acc[nt][half * 2 + 0];
                    Oodd[n * 68 + c0 + 1] = acc[nt][half * 2 + 1];
                }
            }
        }
        __syncthreads();
    }

    // p = 63: last group's final odd rows
    if (gix == 7) {
        for (int i2 = tid; i2 < 2048; i2 += 256) {
            int n = i2 >> 6, d = i2 & 63;
            out_[((size_t)(b * 2048 + n * 64 + 63)) * 256 + h * 64 + d] =
                Oodd[n * 68 + d];
        }
    }
}

// ---------------------------------------------------------------------------
// Launch order: k_qk_adj kept in slot 4 (ncu profiles the 4th launch).
// Deps: prep before qk_adj; build_wx before v2/qk_adj; qk_adj before
// loss/out2; v2 before out2.
// ---------------------------------------------------------------------------
extern "C" void kernel_launch(void* const* d_in, const int* in_sizes, int n_in,
                              void* d_out, int out_size) {
    const float* x  = (const float*)d_in[0];
    const float* W1 = (const float*)d_in[1];
    const float* b1 = (const float*)d_in[2];
    const float* W2 = (const float*)d_in[3];
    const float* b2 = (const float*)d_in[4];
    const float* Wv = (const float*)d_in[5];
    const float* bv = (const float*)d_in[6];
    float* out = (float*)d_out;

    cudaFuncSetAttribute(k_qk_adj, cudaFuncAttributeMaxDynamicSharedMemorySize,
                         SMEM_QK);

    k_build_wx<<<4096, 256>>>(x);
    k_v2<<<M_V / 64, 256>>>(Wv, bv);
    k_prep<<<1, 256>>>(W1, b1, W2, b2);
    k_qk_adj<<<NBHW, 256, SMEM_QK>>>();
    if (out_size > OUT_ELEMS) {
        k_loss_zero<<<1, 1>>>(out);
        k_loss<<<524288 / 256, 256>>>(out);
    }
    k_out2<<<128 * 8, 256>>>(out);
}